// round 15
// baseline (speedup 1.0000x reference)
#include <cuda_runtime.h>

// B=16, C=2048, H=2, HS=64, HOD=1, D_MODEL=2
// Collapsed: M_h = Wq_h Wk_h^T (2x2), g_h = Wv_h Wo_h (2,)
//   t(c,f) = xp_c^T M_h xp_f / 8;  o_h(c) = sum_{f<=c} e^t (g_h.xp_f) / sum e^t
// Taylor degree 10: e^{p.y} = sum_{j+i<=10} (p0^j/j!)(p1^i/i!) y0^j y1^i
// => causal sums = polynomial in prefix moments M_{j,i} = sum_f y0^j y1^i (j+i<=11).
// Chunk = 32 f (64 chunks). K1 power-table dots -> g_mom [b][m][chunk] (transposed,
// coalesced). K2: 16x float4 fully-unrolled MLP prefix (one L2 round-trip),
// row-factored degree-10 poly, exact tails <= 32 (uniform). PDL kept.

#define CC    2048
#define NMOM  78            // #{(j,i): j+i<=11}
#define LOG2E 1.4426950408889634f

__device__ float g_mom[16][NMOM][64];   // [batch][moment][chunk32] chunk-contiguous

__device__ __forceinline__ float ex2f(float v) {
    float y;
    asm("ex2.approx.ftz.f32 %0, %1;" : "=f"(y) : "f"(v));
    return y;
}

// ---------------- K1: chunk moments via smem power tables ----------------
// grid = 128 (b = bid>>3, window r = bid&7), 640 threads.
__global__ __launch_bounds__(640, 1)
void k1_moments(const float* __restrict__ x)
{
    __shared__ float sP0[8][12][33];   // y0^j per chunk32, pad 33 (conflict-free)
    __shared__ float sP1[8][12][33];   // y1^i

    const int tid = threadIdx.x;
    const int b   = blockIdx.x >> 3;
    const int r   = blockIdx.x & 7;

    if (tid < 256) {
        const int ch = tid >> 5, fl = tid & 31;
        const int f  = r * 256 + tid;
        const float2 v = reinterpret_cast<const float2*>(x)[b * CC + f];
        const float y0 = v.x + sinf((float)f);
        const float y1 = v.y + cosf((float)f);
        float p = 1.f, q = 1.f;
        #pragma unroll
        for (int j = 0; j < 12; ++j) {
            sP0[ch][j][fl] = p;  p *= y0;
            sP1[ch][j][fl] = q;  q *= y1;
        }
    }
    __syncthreads();

    if (tid < 8 * NMOM) {              // 624 dot threads
        const int m  = tid >> 3;       // moment index (consecutive tid -> same m)
        const int ch = tid & 7;        // chunk within window -> coalesced stores
        int j = 0, mm = m;
        while (mm >= 12 - j) { mm -= 12 - j; ++j; }   // decode (j, i), rows of 12-j
        const int i = mm;
        const float* __restrict__ P0 = sP0[ch][j];
        const float* __restrict__ P1 = sP1[ch][i];
        float a0 = 0.f, a1 = 0.f, a2 = 0.f, a3 = 0.f;
        #pragma unroll
        for (int f = 0; f < 32; f += 4) {
            a0 = fmaf(P0[f + 0], P1[f + 0], a0);
            a1 = fmaf(P0[f + 1], P1[f + 1], a1);
            a2 = fmaf(P0[f + 2], P1[f + 2], a2);
            a3 = fmaf(P0[f + 3], P1[f + 3], a3);
        }
        g_mom[b][m][8 * r + ch] = (a0 + a1) + (a2 + a3);
    }

    // publish: make g_mom visible, then allow the dependent grid to consume
    __syncthreads();
    __threadfence();
    asm volatile("griddepcontrol.launch_dependents;" ::: "memory");
}

// ---------------- K2: evaluation ----------------
// grid = 128 (b = bid>>3, window r = bid&7), 1024 threads.
// sub = tid>>8: {0: h0-poly, 1: h1-poly, 2: h0-tail, 3: h1-tail}; uniform barriers.
__global__ __launch_bounds__(1024, 1)
void k2_eval(const float* __restrict__ x,
             const float* __restrict__ Wq,
             const float* __restrict__ Wk,
             const float* __restrict__ Wv,
             const float* __restrict__ Wo,
             const float* __restrict__ Wb,
             float* __restrict__ out)
{
    __shared__ float2 sY[256];          // xp window
    __shared__ float  sPre[8][NMOM];    // prefix over chunks < 8r+quad
    __shared__ float  sM[2][2][2];      // M[h][i][j]
    __shared__ float  sG[2][2];         // g[h][i]
    __shared__ float4 sPart[256][4];    // per-(c,sub) partials {den/sd, a0/s0, a1/s1}

    const int tid = threadIdx.x;
    const int b   = blockIdx.x >> 3;
    const int r   = blockIdx.x & 7;

    // ---- concurrent setup: [0,256) sY | [256,448) dots | [448,526) prefixes ----
    if (tid < 256) {
        const int f = r * 256 + tid;
        const float2 v = reinterpret_cast<const float2*>(x)[b * CC + f];
        sY[tid] = make_float2(v.x + sinf((float)f), v.y + cosf((float)f));
    } else if (tid < 448) {
        const int grp = (tid - 256) >> 4, l16 = tid & 15;
        const float *pa, *pb;
        if (grp < 8) {
            const int h = grp >> 2, i = (grp >> 1) & 1, jj = grp & 1;
            pa = Wq + h * 128 + i * 64;
            pb = Wk + h * 128 + jj * 64;
        } else {
            const int g2 = grp - 8, h = g2 >> 1, i = g2 & 1;
            pa = Wv + h * 128 + i * 64;
            pb = Wo + h * 64;
        }
        float s = 0.f;
        #pragma unroll
        for (int e = 0; e < 4; ++e) s = fmaf(pa[l16 * 4 + e], pb[l16 * 4 + e], s);
        #pragma unroll
        for (int off = 8; off; off >>= 1) s += __shfl_down_sync(0xffffffffu, s, off, 16);
        if (l16 == 0) {
            if (grp < 8) sM[grp >> 2][(grp >> 1) & 1][grp & 1] = s;
            else         sG[(grp - 8) >> 1][(grp - 8) & 1]     = s;
        }
    } else if (tid < 448 + NMOM) {
        asm volatile("griddepcontrol.wait;" ::: "memory");   // K1 done/published
        // MLP prefix: 16 independent float4 loads (fully unrolled), then scan
        const int m = tid - 448;
        const float4* __restrict__ vp = reinterpret_cast<const float4*>(g_mom[b][m]);
        float v[64];
        #pragma unroll
        for (int g = 0; g < 16; ++g) {
            const float4 vv = vp[g];
            v[4 * g + 0] = vv.x;  v[4 * g + 1] = vv.y;
            v[4 * g + 2] = vv.z;  v[4 * g + 3] = vv.w;
        }
        float s = 0.f;
        const int base = 8 * r;
        #pragma unroll
        for (int k = 0; k < 64; ++k) {
            if (k >= base && k < base + 8) sPre[k - base][m] = s;
            if (k < base + 7) s += v[k];
        }
    }
    __syncthreads();

    const int c_loc = tid & 255;
    const int sub   = tid >> 8;
    const int h     = sub & 1;
    const int type  = sub >> 1;         // 0 = poly, 1 = tail
    const int quad  = c_loc >> 5;       // chunk32 within window, warp-uniform

    const float2 yc = sY[c_loc];
    const float p0 = (sM[h][0][0] * yc.x + sM[h][1][0] * yc.y) * 0.125f;
    const float p1 = (sM[h][0][1] * yc.x + sM[h][1][1] * yc.y) * 0.125f;

    if (type == 0) {
        // ---- poly (row-factorized, degree 10): sums over f < 32*(8r+quad) ----
        const float INV[12] = {0.f, 1.f, 0.5f, 1.f/3.f, 0.25f, 0.2f, 1.f/6.f,
                               1.f/7.f, 0.125f, 1.f/9.f, 0.1f, 1.f/11.f};
        float aq[12], bq[12];
        aq[0] = 1.f; bq[0] = 1.f;
        #pragma unroll
        for (int t = 1; t < 12; ++t) {
            aq[t] = aq[t - 1] * p0 * INV[t];
            bq[t] = bq[t - 1] * p1 * INV[t];
        }
        const float* PRE = sPre[quad];
        float sd = 0.f, s0 = 0.f, s1 = 0.f;
        #pragma unroll
        for (int J = 0; J <= 11; ++J) {
            const int ro = J * 12 - (J * (J - 1)) / 2;
            float rt = 0.f, rs = 0.f, Plast = 0.f;
            #pragma unroll
            for (int I = 0; I + J <= 11; ++I) {
                const float P = PRE[ro + I];
                if (I + J <= 10) rt = fmaf(bq[I], P, rt);       // r_trunc (den)
                if (I >= 1)      rs = fmaf(bq[I - 1], P, rs);   // r_shift (A1)
                if (I + J == 11) Plast = P;
            }
            const float rf = fmaf(bq[11 - J], Plast, rt);       // r_full (A0)
            if (J <= 10) sd = fmaf(aq[J], rt, sd);
            if (J >= 1)  s0 = fmaf(aq[J - 1], rf, s0);
            s1 = fmaf(aq[J], rs, s1);
        }
        sPart[c_loc][sub] = make_float4(sd, s0, s1, 0.f);
    } else {
        // ---- exact tail over f in [32*chunk(c), c]  (<= 32 iterations) ----
        const float pd0 = p0 * LOG2E, pd1 = p1 * LOG2E;
        float den = 0.f, a0 = 0.f, a1 = 0.f;
        for (int fl = c_loc & ~31; fl <= c_loc; ++fl) {
            const float2 yf = sY[fl];
            const float e = ex2f(fmaf(yf.x, pd0, yf.y * pd1));
            den += e; a0 = fmaf(e, yf.x, a0); a1 = fmaf(e, yf.y, a1);
        }
        sPart[c_loc][sub] = make_float4(den, a0, a1, 0.f);
    }
    __syncthreads();

    // ---- folded epilogue: sub 0 combines both heads and writes out ----
    if (sub == 0) {
        const float4 P0h = sPart[c_loc][0];   // h0 poly
        const float4 P1h = sPart[c_loc][1];   // h1 poly
        const float4 T0h = sPart[c_loc][2];   // h0 tail
        const float4 T1h = sPart[c_loc][3];   // h1 tail
        const float o0 = (sG[0][0] * (P0h.y + T0h.y) + sG[0][1] * (P0h.z + T0h.z))
                         / (P0h.x + T0h.x);
        const float o1 = (sG[1][0] * (P1h.y + T1h.y) + sG[1][1] * (P1h.z + T1h.z))
                         / (P1h.x + T1h.x);
        const float b00 = __ldg(Wb + 0), b01 = __ldg(Wb + 1);
        const float b10 = __ldg(Wb + 2), b11 = __ldg(Wb + 3);
        float2 res;
        res.x = fmaf(o0, b00, o1 * b10);
        res.y = fmaf(o0, b01, o1 * b11);
        reinterpret_cast<float2*>(out)[b * CC + r * 256 + c_loc] = res;
    }
}

extern "C" void kernel_launch(void* const* d_in, const int* in_sizes, int n_in,
                              void* d_out, int out_size)
{
    const float* x  = (const float*)d_in[0];
    const float* Wq = (const float*)d_in[1];
    const float* Wk = (const float*)d_in[2];
    const float* Wv = (const float*)d_in[3];
    const float* Wo = (const float*)d_in[4];
    const float* Wb = (const float*)d_in[5];
    float* out = (float*)d_out;

    k1_moments<<<128, 640>>>(x);

    // K2 with programmatic stream serialization: it may begin while K1 drains;
    // its g_mom consumers gate on griddepcontrol.wait.
    cudaLaunchConfig_t cfg = {};
    cfg.gridDim  = dim3(128);
    cfg.blockDim = dim3(1024);
    cudaLaunchAttribute attrs[1];
    attrs[0].id = cudaLaunchAttributeProgrammaticStreamSerialization;
    attrs[0].val.programmaticStreamSerializationAllowed = 1;
    cfg.attrs    = attrs;
    cfg.numAttrs = 1;
    cudaLaunchKernelEx(&cfg, k2_eval, x, Wq, Wk, Wv, Wo, Wb, out);
}

// round 16
// speedup vs baseline: 1.0174x; 1.0174x over previous
#include <cuda_runtime.h>

// B=16, C=2048, H=2, HS=64, HOD=1, D_MODEL=2
// Collapsed: M_h = Wq_h Wk_h^T (2x2), g_h = Wv_h Wo_h (2,)
//   t(c,f) = xp_c^T M_h xp_f / 8;  o_h(c) = sum_{f<=c} e^t (g_h.xp_f) / sum e^t
// Taylor degree 10 => causal sums = poly in prefix moments M_{j,i} (j+i<=11).
// Chunk = 64 f (32 chunks). K1 (128x512) power-table dots -> g_mom[b][chunk][m].
// K2 (256x512): window = 128 queries, 2 blocks/SM co-resident for latency hiding;
// v[32] MLP prefix, row-factored poly, exact tails <= 64, folded epilogue. PDL.

#define CC    2048
#define NMOM  78            // #{(j,i): j+i<=11}
#define LOG2E 1.4426950408889634f

__device__ float g_mom[16][32][NMOM];   // per (batch, chunk64) raw moments

__device__ __forceinline__ float ex2f(float v) {
    float y;
    asm("ex2.approx.ftz.f32 %0, %1;" : "=f"(y) : "f"(v));
    return y;
}

// ---------------- K1: chunk moments via smem power tables ----------------
// grid = 128 (b = bid>>3, window256 r = bid&7), 512 threads.
__global__ __launch_bounds__(512, 1)
void k1_moments(const float* __restrict__ x)
{
    __shared__ float sP0[4][12][67];   // y0^j per chunk64, pad 67 (conflict-free)
    __shared__ float sP1[4][12][67];   // y1^i

    const int tid = threadIdx.x;
    const int b   = blockIdx.x >> 3;
    const int r   = blockIdx.x & 7;

    if (tid < 256) {
        const int ch = tid >> 6, fl = tid & 63;
        const int f  = r * 256 + tid;
        const float2 v = reinterpret_cast<const float2*>(x)[b * CC + f];
        const float y0 = v.x + sinf((float)f);
        const float y1 = v.y + cosf((float)f);
        float p = 1.f, q = 1.f;
        #pragma unroll
        for (int j = 0; j < 12; ++j) {
            sP0[ch][j][fl] = p;  p *= y0;
            sP1[ch][j][fl] = q;  q *= y1;
        }
    }
    __syncthreads();

    if (tid < 4 * NMOM) {              // 312 dot threads
        const int ch = tid / NMOM;
        const int m  = tid % NMOM;
        int j = 0, mm = m;
        while (mm >= 12 - j) { mm -= 12 - j; ++j; }   // decode (j, i), rows of 12-j
        const int i = mm;
        const float* __restrict__ P0 = sP0[ch][j];
        const float* __restrict__ P1 = sP1[ch][i];
        float a0 = 0.f, a1 = 0.f, a2 = 0.f, a3 = 0.f;
        #pragma unroll
        for (int f = 0; f < 64; f += 4) {
            a0 = fmaf(P0[f + 0], P1[f + 0], a0);
            a1 = fmaf(P0[f + 1], P1[f + 1], a1);
            a2 = fmaf(P0[f + 2], P1[f + 2], a2);
            a3 = fmaf(P0[f + 3], P1[f + 3], a3);
        }
        g_mom[b][4 * r + ch][m] = (a0 + a1) + (a2 + a3);
    }

    // publish: make g_mom visible, then allow the dependent grid to consume
    __syncthreads();
    __threadfence();
    asm volatile("griddepcontrol.launch_dependents;" ::: "memory");
}

// ---------------- K2: evaluation ----------------
// grid = 256 (b = bid>>4, window128 r = bid&15), 512 threads; 2 blocks/SM.
// sub = tid>>7: {0: h0-poly, 1: h1-poly, 2: h0-tail, 3: h1-tail}; uniform barriers.
__global__ __launch_bounds__(512, 2)
void k2_eval(const float* __restrict__ x,
             const float* __restrict__ Wq,
             const float* __restrict__ Wk,
             const float* __restrict__ Wv,
             const float* __restrict__ Wo,
             const float* __restrict__ Wb,
             float* __restrict__ out)
{
    __shared__ float2 sY[128];          // xp window
    __shared__ float  sPre[2][NMOM];    // prefix over chunks < 2r+quad
    __shared__ float  sM[2][2][2];      // M[h][i][j]
    __shared__ float  sG[2][2];         // g[h][i]
    __shared__ float4 sPart[128][4];    // per-(c,sub) partials {den/sd, a0/s0, a1/s1}

    const int tid = threadIdx.x;
    const int b   = blockIdx.x >> 4;
    const int r   = blockIdx.x & 15;

    // ---- concurrent setup: [0,128) sY | [128,320) dots | [320,398) prefixes ----
    if (tid < 128) {
        const int f = r * 128 + tid;
        const float2 v = reinterpret_cast<const float2*>(x)[b * CC + f];
        sY[tid] = make_float2(v.x + sinf((float)f), v.y + cosf((float)f));
    } else if (tid < 320) {
        const int grp = (tid - 128) >> 4, l16 = tid & 15;
        const float *pa, *pb;
        if (grp < 8) {
            const int h = grp >> 2, i = (grp >> 1) & 1, jj = grp & 1;
            pa = Wq + h * 128 + i * 64;
            pb = Wk + h * 128 + jj * 64;
        } else {
            const int g2 = grp - 8, h = g2 >> 1, i = g2 & 1;
            pa = Wv + h * 128 + i * 64;
            pb = Wo + h * 64;
        }
        float s = 0.f;
        #pragma unroll
        for (int e = 0; e < 4; ++e) s = fmaf(pa[l16 * 4 + e], pb[l16 * 4 + e], s);
        #pragma unroll
        for (int off = 8; off; off >>= 1) s += __shfl_down_sync(0xffffffffu, s, off, 16);
        if (l16 == 0) {
            if (grp < 8) sM[grp >> 2][(grp >> 1) & 1][grp & 1] = s;
            else         sG[(grp - 8) >> 1][(grp - 8) & 1]     = s;
        }
    } else if (tid < 320 + NMOM) {
        asm volatile("griddepcontrol.wait;" ::: "memory");   // K1 done/published
        // MLP prefix: unconditional preload of all 32 chunk values, then scan
        const int m = tid - 320;
        float v[32];
        #pragma unroll
        for (int k = 0; k < 32; ++k) v[k] = g_mom[b][k][m];
        float s = 0.f;
        const int base = 2 * r;
        #pragma unroll
        for (int k = 0; k < 32; ++k) {
            if (k >= base && k < base + 2) sPre[k - base][m] = s;
            if (k < base + 1) s += v[k];
        }
    }
    __syncthreads();

    const int c_loc = tid & 127;
    const int sub   = tid >> 7;
    const int h     = sub & 1;
    const int type  = sub >> 1;         // 0 = poly, 1 = tail
    const int quad  = c_loc >> 6;       // chunk64 within window (0..1), warp-uniform

    const float2 yc = sY[c_loc];
    const float p0 = (sM[h][0][0] * yc.x + sM[h][1][0] * yc.y) * 0.125f;
    const float p1 = (sM[h][0][1] * yc.x + sM[h][1][1] * yc.y) * 0.125f;

    if (type == 0) {
        // ---- poly (row-factorized, degree 10): sums over f < 64*(2r+quad) ----
        const float INV[12] = {0.f, 1.f, 0.5f, 1.f/3.f, 0.25f, 0.2f, 1.f/6.f,
                               1.f/7.f, 0.125f, 1.f/9.f, 0.1f, 1.f/11.f};
        float aq[12], bq[12];
        aq[0] = 1.f; bq[0] = 1.f;
        #pragma unroll
        for (int t = 1; t < 12; ++t) {
            aq[t] = aq[t - 1] * p0 * INV[t];
            bq[t] = bq[t - 1] * p1 * INV[t];
        }
        const float* PRE = sPre[quad];
        float sd = 0.f, s0 = 0.f, s1 = 0.f;
        #pragma unroll
        for (int J = 0; J <= 11; ++J) {
            const int ro = J * 12 - (J * (J - 1)) / 2;
            float rt = 0.f, rs = 0.f, Plast = 0.f;
            #pragma unroll
            for (int I = 0; I + J <= 11; ++I) {
                const float P = PRE[ro + I];
                if (I + J <= 10) rt = fmaf(bq[I], P, rt);       // r_trunc (den)
                if (I >= 1)      rs = fmaf(bq[I - 1], P, rs);   // r_shift (A1)
                if (I + J == 11) Plast = P;
            }
            const float rf = fmaf(bq[11 - J], Plast, rt);       // r_full (A0)
            if (J <= 10) sd = fmaf(aq[J], rt, sd);
            if (J >= 1)  s0 = fmaf(aq[J - 1], rf, s0);
            s1 = fmaf(aq[J], rs, s1);
        }
        sPart[c_loc][sub] = make_float4(sd, s0, s1, 0.f);
    } else {
        // ---- exact tail over f in [64*chunk(c), c]  (<= 64 iterations) ----
        const float pd0 = p0 * LOG2E, pd1 = p1 * LOG2E;
        float den = 0.f, a0 = 0.f, a1 = 0.f;
        for (int fl = c_loc & ~63; fl <= c_loc; ++fl) {
            const float2 yf = sY[fl];
            const float e = ex2f(fmaf(yf.x, pd0, yf.y * pd1));
            den += e; a0 = fmaf(e, yf.x, a0); a1 = fmaf(e, yf.y, a1);
        }
        sPart[c_loc][sub] = make_float4(den, a0, a1, 0.f);
    }
    __syncthreads();

    // ---- folded epilogue: sub 0 combines both heads and writes out ----
    if (sub == 0) {
        const float4 P0h = sPart[c_loc][0];   // h0 poly
        const float4 P1h = sPart[c_loc][1];   // h1 poly
        const float4 T0h = sPart[c_loc][2];   // h0 tail
        const float4 T1h = sPart[c_loc][3];   // h1 tail
        const float o0 = (sG[0][0] * (P0h.y + T0h.y) + sG[0][1] * (P0h.z + T0h.z))
                         / (P0h.x + T0h.x);
        const float o1 = (sG[1][0] * (P1h.y + T1h.y) + sG[1][1] * (P1h.z + T1h.z))
                         / (P1h.x + T1h.x);
        const float b00 = __ldg(Wb + 0), b01 = __ldg(Wb + 1);
        const float b10 = __ldg(Wb + 2), b11 = __ldg(Wb + 3);
        float2 res;
        res.x = fmaf(o0, b00, o1 * b10);
        res.y = fmaf(o0, b01, o1 * b11);
        reinterpret_cast<float2*>(out)[b * CC + r * 128 + c_loc] = res;
    }
}

extern "C" void kernel_launch(void* const* d_in, const int* in_sizes, int n_in,
                              void* d_out, int out_size)
{
    const float* x  = (const float*)d_in[0];
    const float* Wq = (const float*)d_in[1];
    const float* Wk = (const float*)d_in[2];
    const float* Wv = (const float*)d_in[3];
    const float* Wo = (const float*)d_in[4];
    const float* Wb = (const float*)d_in[5];
    float* out = (float*)d_out;

    k1_moments<<<128, 512>>>(x);

    // K2 with programmatic stream serialization: may begin while K1 drains;
    // its g_mom consumers gate on griddepcontrol.wait.
    cudaLaunchConfig_t cfg = {};
    cfg.gridDim  = dim3(256);
    cfg.blockDim = dim3(512);
    cudaLaunchAttribute attrs[1];
    attrs[0].id = cudaLaunchAttributeProgrammaticStreamSerialization;
    attrs[0].val.programmaticStreamSerializationAllowed = 1;
    cfg.attrs    = attrs;
    cfg.numAttrs = 1;
    cudaLaunchKernelEx(&cfg, k2_eval, x, Wq, Wk, Wv, Wo, Wb, out);
}

// round 17
// speedup vs baseline: 1.0701x; 1.0518x over previous
#include <cuda_runtime.h>

// B=16, C=2048, H=2, HS=64, HOD=1, D_MODEL=2
// Collapsed: M_h = Wq_h Wk_h^T (2x2), g_h = Wv_h Wo_h (2,)
//   t(c,f) = xp_c^T M_h xp_f / 8;  o_h(c) = sum_{f<=c} e^t (g_h.xp_f) / sum e^t
// Taylor degree 10 => causal sums = poly in prefix moments M_{j,i} (j+i<=11).
// Chunk = 64 f (32 chunks). K1 (128x512) power-table dots -> g_mom[b][chunk][m].
// K2 (256x512, 2 blocks/SM): slots {poly-h0, poly-h1, tail-both-lo, tail-both-hi}.
// Tails process BOTH heads via packed fma.rn.f32x2 (exact fp32) over <=32 f each.

#define CC    2048
#define NMOM  78            // #{(j,i): j+i<=11}
#define LOG2E 1.4426950408889634f

__device__ float g_mom[16][32][NMOM];   // per (batch, chunk64) raw moments

__device__ __forceinline__ float ex2f(float v) {
    float y;
    asm("ex2.approx.ftz.f32 %0, %1;" : "=f"(y) : "f"(v));
    return y;
}

// ---------------- K1: chunk moments via smem power tables ----------------
__global__ __launch_bounds__(512, 1)
void k1_moments(const float* __restrict__ x)
{
    __shared__ float sP0[4][12][67];
    __shared__ float sP1[4][12][67];

    const int tid = threadIdx.x;
    const int b   = blockIdx.x >> 3;
    const int r   = blockIdx.x & 7;

    if (tid < 256) {
        const int ch = tid >> 6, fl = tid & 63;
        const int f  = r * 256 + tid;
        const float2 v = reinterpret_cast<const float2*>(x)[b * CC + f];
        const float y0 = v.x + sinf((float)f);
        const float y1 = v.y + cosf((float)f);
        float p = 1.f, q = 1.f;
        #pragma unroll
        for (int j = 0; j < 12; ++j) {
            sP0[ch][j][fl] = p;  p *= y0;
            sP1[ch][j][fl] = q;  q *= y1;
        }
    }
    __syncthreads();

    if (tid < 4 * NMOM) {
        const int ch = tid / NMOM;
        const int m  = tid % NMOM;
        int j = 0, mm = m;
        while (mm >= 12 - j) { mm -= 12 - j; ++j; }
        const int i = mm;
        const float* __restrict__ P0 = sP0[ch][j];
        const float* __restrict__ P1 = sP1[ch][i];
        float a0 = 0.f, a1 = 0.f, a2 = 0.f, a3 = 0.f;
        #pragma unroll
        for (int f = 0; f < 64; f += 4) {
            a0 = fmaf(P0[f + 0], P1[f + 0], a0);
            a1 = fmaf(P0[f + 1], P1[f + 1], a1);
            a2 = fmaf(P0[f + 2], P1[f + 2], a2);
            a3 = fmaf(P0[f + 3], P1[f + 3], a3);
        }
        g_mom[b][4 * r + ch][m] = (a0 + a1) + (a2 + a3);
    }

    __syncthreads();
    __threadfence();
    asm volatile("griddepcontrol.launch_dependents;" ::: "memory");
}

// ---------------- K2: evaluation ----------------
// grid = 256 (b = bid>>4, window128 r = bid&15), 512 threads; 2 blocks/SM.
// sub: 0 = h0 poly, 1 = h1 poly, 2 = tail-both f<fs+32, 3 = tail-both f>=fs+32.
__global__ __launch_bounds__(512, 2)
void k2_eval(const float* __restrict__ x,
             const float* __restrict__ Wq,
             const float* __restrict__ Wk,
             const float* __restrict__ Wv,
             const float* __restrict__ Wo,
             const float* __restrict__ Wb,
             float* __restrict__ out)
{
    __shared__ float4 sY[128];          // {y0, y0, y1, y1}
    __shared__ float  sPre[2][NMOM];
    __shared__ float  sM[2][2][2];
    __shared__ float  sG[2][2];
    __shared__ float4 sPart[128][6];    // 0:polyh0 1:polyh1 2,3:lo(h0,h1) 4,5:hi(h0,h1)

    const int tid = threadIdx.x;
    const int b   = blockIdx.x >> 4;
    const int r   = blockIdx.x & 15;

    // ---- concurrent setup: [0,128) sY | [128,320) dots | [320,398) prefixes ----
    if (tid < 128) {
        const int f = r * 128 + tid;
        const float2 v = reinterpret_cast<const float2*>(x)[b * CC + f];
        const float y0 = v.x + sinf((float)f);
        const float y1 = v.y + cosf((float)f);
        sY[tid] = make_float4(y0, y0, y1, y1);
    } else if (tid < 320) {
        const int grp = (tid - 128) >> 4, l16 = tid & 15;
        const float *pa, *pb;
        if (grp < 8) {
            const int h = grp >> 2, i = (grp >> 1) & 1, jj = grp & 1;
            pa = Wq + h * 128 + i * 64;
            pb = Wk + h * 128 + jj * 64;
        } else {
            const int g2 = grp - 8, h = g2 >> 1, i = g2 & 1;
            pa = Wv + h * 128 + i * 64;
            pb = Wo + h * 64;
        }
        float s = 0.f;
        #pragma unroll
        for (int e = 0; e < 4; ++e) s = fmaf(pa[l16 * 4 + e], pb[l16 * 4 + e], s);
        #pragma unroll
        for (int off = 8; off; off >>= 1) s += __shfl_down_sync(0xffffffffu, s, off, 16);
        if (l16 == 0) {
            if (grp < 8) sM[grp >> 2][(grp >> 1) & 1][grp & 1] = s;
            else         sG[(grp - 8) >> 1][(grp - 8) & 1]     = s;
        }
    } else if (tid < 320 + NMOM) {
        asm volatile("griddepcontrol.wait;" ::: "memory");
        const int m = tid - 320;
        float v[32];
        #pragma unroll
        for (int k = 0; k < 32; ++k) v[k] = g_mom[b][k][m];
        float s = 0.f;
        const int base = 2 * r;
        #pragma unroll
        for (int k = 0; k < 32; ++k) {
            if (k >= base && k < base + 2) sPre[k - base][m] = s;
            if (k < base + 1) s += v[k];
        }
    }
    __syncthreads();

    const int c_loc = tid & 127;
    const int sub   = tid >> 7;
    const int quad  = c_loc >> 6;       // chunk64 within window (0..1), warp-uniform

    const float4 yc = sY[c_loc];
    // yc.x = y0(c), yc.z = y1(c)

    if (sub < 2) {
        // ---- poly (row-factorized, degree 10), head = sub ----
        const int h = sub;
        const float p0 = (sM[h][0][0] * yc.x + sM[h][1][0] * yc.z) * 0.125f;
        const float p1 = (sM[h][0][1] * yc.x + sM[h][1][1] * yc.z) * 0.125f;
        const float INV[12] = {0.f, 1.f, 0.5f, 1.f/3.f, 0.25f, 0.2f, 1.f/6.f,
                               1.f/7.f, 0.125f, 1.f/9.f, 0.1f, 1.f/11.f};
        float aq[12], bq[12];
        aq[0] = 1.f; bq[0] = 1.f;
        #pragma unroll
        for (int t = 1; t < 12; ++t) {
            aq[t] = aq[t - 1] * p0 * INV[t];
            bq[t] = bq[t - 1] * p1 * INV[t];
        }
        const float* PRE = sPre[quad];
        float sd = 0.f, s0 = 0.f, s1 = 0.f;
        #pragma unroll
        for (int J = 0; J <= 11; ++J) {
            const int ro = J * 12 - (J * (J - 1)) / 2;
            float rt = 0.f, rs = 0.f, Plast = 0.f;
            #pragma unroll
            for (int I = 0; I + J <= 11; ++I) {
                const float P = PRE[ro + I];
                if (I + J <= 10) rt = fmaf(bq[I], P, rt);
                if (I >= 1)      rs = fmaf(bq[I - 1], P, rs);
                if (I + J == 11) Plast = P;
            }
            const float rf = fmaf(bq[11 - J], Plast, rt);
            if (J <= 10) sd = fmaf(aq[J], rt, sd);
            if (J >= 1)  s0 = fmaf(aq[J - 1], rf, s0);
            s1 = fmaf(aq[J], rs, s1);
        }
        sPart[c_loc][sub] = make_float4(sd, s0, s1, 0.f);
    } else {
        // ---- packed both-head exact tail (fma.rn.f32x2 = exact fp32) ----
        const float pd00 = (sM[0][0][0] * yc.x + sM[0][1][0] * yc.z) * (0.125f * LOG2E);
        const float pd01 = (sM[0][0][1] * yc.x + sM[0][1][1] * yc.z) * (0.125f * LOG2E);
        const float pd10 = (sM[1][0][0] * yc.x + sM[1][1][0] * yc.z) * (0.125f * LOG2E);
        const float pd11 = (sM[1][0][1] * yc.x + sM[1][1][1] * yc.z) * (0.125f * LOG2E);
        unsigned long long Pa, Pb;
        asm("mov.b64 %0, {%1, %2};" : "=l"(Pa) : "f"(pd00), "f"(pd10)); // lo = h0
        asm("mov.b64 %0, {%1, %2};" : "=l"(Pb) : "f"(pd01), "f"(pd11));

        const int fs   = c_loc & ~63;
        const int fmid = fs + 32;
        int f0, f1;
        if (sub == 2) { f0 = fs;   f1 = (c_loc + 1 < fmid) ? (c_loc + 1) : fmid; }
        else          { f0 = fmid; f1 = c_loc + 1; }   // may be empty

        unsigned long long dacc = 0ull, a0acc = 0ull, a1acc = 0ull;  // packed {0,0}
        unsigned ay = (unsigned)__cvta_generic_to_shared(&sY[0]) + 16u * f0;
        for (int fl = f0; fl < f1; ++fl) {
            unsigned long long xx, yy, aa, ee;
            asm("ld.shared.v2.b64 {%0, %1}, [%2];" : "=l"(xx), "=l"(yy) : "r"(ay));
            asm("mul.rn.f32x2 %0, %1, %2;"       : "=l"(aa) : "l"(xx), "l"(Pa));
            asm("fma.rn.f32x2 %0, %1, %2, %0;"   : "+l"(aa) : "l"(yy), "l"(Pb));
            float alo, ahi;
            asm("mov.b64 {%0, %1}, %2;" : "=f"(alo), "=f"(ahi) : "l"(aa));
            const float e0 = ex2f(alo);
            const float e1 = ex2f(ahi);
            asm("mov.b64 %0, {%1, %2};" : "=l"(ee) : "f"(e0), "f"(e1));
            asm("add.rn.f32x2 %0, %0, %1;"     : "+l"(dacc)  : "l"(ee));
            asm("fma.rn.f32x2 %0, %1, %2, %0;" : "+l"(a0acc) : "l"(ee), "l"(xx));
            asm("fma.rn.f32x2 %0, %1, %2, %0;" : "+l"(a1acc) : "l"(ee), "l"(yy));
            ay += 16u;
        }
        float d0, d1, u0, u1, w0, w1;
        asm("mov.b64 {%0, %1}, %2;" : "=f"(d0), "=f"(d1) : "l"(dacc));
        asm("mov.b64 {%0, %1}, %2;" : "=f"(u0), "=f"(u1) : "l"(a0acc));
        asm("mov.b64 {%0, %1}, %2;" : "=f"(w0), "=f"(w1) : "l"(a1acc));
        const int s0i = (sub == 2) ? 2 : 4;
        sPart[c_loc][s0i + 0] = make_float4(d0, u0, w0, 0.f);  // h0
        sPart[c_loc][s0i + 1] = make_float4(d1, u1, w1, 0.f);  // h1
    }
    __syncthreads();

    // ---- folded epilogue: sub 0 combines both heads and writes out ----
    if (sub == 0) {
        const float4 Ph0 = sPart[c_loc][0];
        const float4 Ph1 = sPart[c_loc][1];
        const float4 L0  = sPart[c_loc][2];
        const float4 L1  = sPart[c_loc][3];
        const float4 H0  = sPart[c_loc][4];
        const float4 H1  = sPart[c_loc][5];
        const float den0 = Ph0.x + L0.x + H0.x;
        const float A00  = Ph0.y + L0.y + H0.y;
        const float A10  = Ph0.z + L0.z + H0.z;
        const float den1 = Ph1.x + L1.x + H1.x;
        const float A01  = Ph1.y + L1.y + H1.y;
        const float A11  = Ph1.z + L1.z + H1.z;
        const float o0 = (sG[0][0] * A00 + sG[0][1] * A10) / den0;
        const float o1 = (sG[1][0] * A01 + sG[1][1] * A11) / den1;
        const float b00 = __ldg(Wb + 0), b01 = __ldg(Wb + 1);
        const float b10 = __ldg(Wb + 2), b11 = __ldg(Wb + 3);
        float2 res;
        res.x = fmaf(o0, b00, o1 * b10);
        res.y = fmaf(o0, b01, o1 * b11);
        reinterpret_cast<float2*>(out)[b * CC + r * 128 + c_loc] = res;
    }
}

extern "C" void kernel_launch(void* const* d_in, const int* in_sizes, int n_in,
                              void* d_out, int out_size)
{
    const float* x  = (const float*)d_in[0];
    const float* Wq = (const float*)d_in[1];
    const float* Wk = (const float*)d_in[2];
    const float* Wv = (const float*)d_in[3];
    const float* Wo = (const float*)d_in[4];
    const float* Wb = (const float*)d_in[5];
    float* out = (float*)d_out;

    k1_moments<<<128, 512>>>(x);

    cudaLaunchConfig_t cfg = {};
    cfg.gridDim  = dim3(256);
    cfg.blockDim = dim3(512);
    cudaLaunchAttribute attrs[1];
    attrs[0].id = cudaLaunchAttributeProgrammaticStreamSerialization;
    attrs[0].val.programmaticStreamSerializationAllowed = 1;
    cfg.attrs    = attrs;
    cfg.numAttrs = 1;
    cudaLaunchKernelEx(&cfg, k2_eval, x, Wq, Wk, Wv, Wo, Wb, out);
}